// round 8
// baseline (speedup 1.0000x reference)
#include <cuda_runtime.h>
#include <cuda_bf16.h>
#include <cstdint>

// Shapes (fixed by the problem)
#define L_DIM 4
#define B_DIM 8
#define C_DIM 256
#define HW    4096           // 64*64
#define LBC   (L_DIM * B_DIM * C_DIM)   // 8192

// Scratch in device globals (no allocations allowed)
__device__ float g_gap[LBC];

// ---------------------------------------------------------------------------
// Kernel 1: GAP over H,W. One block per (l,b,c) plane (4096 contiguous f32).
// 128 threads, each loads 8 float4, warp-shuffle reduce. (Unchanged.)
// Triggers PDL completion as early as possible.
// ---------------------------------------------------------------------------
__global__ __launch_bounds__(128) void gap_kernel(const float* __restrict__ in) {
    const int bc = blockIdx.x;
    const float4* p = reinterpret_cast<const float4*>(in) + (size_t)bc * (HW / 4);
    const int t = threadIdx.x;

    float s = 0.0f;
#pragma unroll
    for (int k = 0; k < 8; ++k) {
        float4 v = p[t + k * 128];
        s += (v.x + v.y) + (v.z + v.w);
    }
#pragma unroll
    for (int o = 16; o > 0; o >>= 1)
        s += __shfl_xor_sync(0xffffffffu, s, o);

    __shared__ float sh[4];
    if ((t & 31) == 0) sh[t >> 5] = s;
    __syncthreads();
    if (t == 0)
        g_gap[bc] = (sh[0] + sh[1] + sh[2] + sh[3]) * (1.0f / (float)HW);

    // Allow the dependent grid to start launching.
    cudaTriggerProgrammaticLaunchCompletion();
}

// ---------------------------------------------------------------------------
// Kernel 2 (FUSED attn+scale, PDL): launched with programmatic dependent
// launch. The 8 plane loads only touch `in` (not written by gap), so they are
// issued BEFORE cudaGridDependencySynchronize(); only the attn-scalar
// computation (which reads g_gap) sits behind the dependency wait. This
// overlaps gap's drain with this kernel's memory ramp.
// ---------------------------------------------------------------------------
__global__ __launch_bounds__(128) void scale_fused_kernel(const float* __restrict__ in,
                                                          const float* __restrict__ Wlin,
                                                          float* __restrict__ out) {
    const int bc = blockIdx.x;                 // (l*B + b)*C + c
    const int l = bc >> 11;                    // /2048
    const int b = (bc >> 8) & 7;
    const int c = bc & 255;
    const int t = threadIdx.x;

    const float4* p = reinterpret_cast<const float4*>(in) + (size_t)bc * (HW / 4);
    float4* o = reinterpret_cast<float4*>(out) + (size_t)bc * (HW / 4);

    // ---- Front-batch all 8 plane loads (independent LDG.128 in flight) ----
    float4 v0 = p[t + 0 * 128];
    float4 v1 = p[t + 1 * 128];
    float4 v2 = p[t + 2 * 128];
    float4 v3 = p[t + 3 * 128];
    float4 v4 = p[t + 4 * 128];
    float4 v5 = p[t + 5 * 128];
    float4 v6 = p[t + 6 * 128];
    float4 v7 = p[t + 7 * 128];

    // Wait for the gap grid's writes to be visible before touching g_gap.
    cudaGridDependencySynchronize();

    // ---- Compute attn scalar while the plane loads are outstanding ----
    const float* wr = Wlin + (size_t)c * C_DIM;
    float pa0 = 0.f, pa1 = 0.f, pa2 = 0.f, pa3 = 0.f;
#pragma unroll
    for (int j = 0; j < 2; ++j) {
        const int c2 = t + 128 * j;
        const float w = wr[c2];
        pa0 = fmaf(w, g_gap[(0 * B_DIM + b) * C_DIM + c2], pa0);
        pa1 = fmaf(w, g_gap[(1 * B_DIM + b) * C_DIM + c2], pa1);
        pa2 = fmaf(w, g_gap[(2 * B_DIM + b) * C_DIM + c2], pa2);
        pa3 = fmaf(w, g_gap[(3 * B_DIM + b) * C_DIM + c2], pa3);
    }
#pragma unroll
    for (int off = 16; off > 0; off >>= 1) {
        pa0 += __shfl_xor_sync(0xffffffffu, pa0, off);
        pa1 += __shfl_xor_sync(0xffffffffu, pa1, off);
        pa2 += __shfl_xor_sync(0xffffffffu, pa2, off);
        pa3 += __shfl_xor_sync(0xffffffffu, pa3, off);
    }
    __shared__ float sh[4][4];                 // [warp][l']
    const int warp = t >> 5;
    if ((t & 31) == 0) {
        sh[warp][0] = pa0; sh[warp][1] = pa1;
        sh[warp][2] = pa2; sh[warp][3] = pa3;
    }
    __syncthreads();
    const float s0 = sh[0][0] + sh[1][0] + sh[2][0] + sh[3][0];
    const float s1 = sh[0][1] + sh[1][1] + sh[2][1] + sh[3][1];
    const float s2 = sh[0][2] + sh[1][2] + sh[2][2] + sh[3][2];
    const float s3 = sh[0][3] + sh[1][3] + sh[2][3] + sh[3][3];

    const float m  = fmaxf(fmaxf(s0, s1), fmaxf(s2, s3));
    const float e0 = __expf(s0 - m), e1 = __expf(s1 - m);
    const float e2 = __expf(s2 - m), e3 = __expf(s3 - m);
    const float inv = 1.0f / (e0 + e1 + e2 + e3);
    const float el  = (l == 0) ? e0 : (l == 1) ? e1 : (l == 2) ? e2 : e3;
    const float a   = el * inv;

    // ---- Scale and store ----
    v0.x *= a; v0.y *= a; v0.z *= a; v0.w *= a;
    v1.x *= a; v1.y *= a; v1.z *= a; v1.w *= a;
    v2.x *= a; v2.y *= a; v2.z *= a; v2.w *= a;
    v3.x *= a; v3.y *= a; v3.z *= a; v3.w *= a;
    v4.x *= a; v4.y *= a; v4.z *= a; v4.w *= a;
    v5.x *= a; v5.y *= a; v5.z *= a; v5.w *= a;
    v6.x *= a; v6.y *= a; v6.z *= a; v6.w *= a;
    v7.x *= a; v7.y *= a; v7.z *= a; v7.w *= a;

    o[t + 0 * 128] = v0;
    o[t + 1 * 128] = v1;
    o[t + 2 * 128] = v2;
    o[t + 3 * 128] = v3;
    o[t + 4 * 128] = v4;
    o[t + 5 * 128] = v5;
    o[t + 6 * 128] = v6;
    o[t + 7 * 128] = v7;
}

extern "C" void kernel_launch(void* const* d_in, const int* in_sizes, int n_in,
                              void* d_out, int out_size) {
    const float* inputs = (const float*)d_in[0];   // [L,B,C,H,W] f32
    const float* Wlin   = (const float*)d_in[1];   // [C,C] f32
    float* out = (float*)d_out;

    gap_kernel<<<LBC, 128>>>(inputs);

    // Dependent launch: allow this grid to launch as the gap grid drains.
    cudaLaunchConfig_t cfg = {};
    cfg.gridDim  = dim3(LBC);
    cfg.blockDim = dim3(128);
    cfg.dynamicSmemBytes = 0;
    cfg.stream = 0;
    cudaLaunchAttribute attrs[1];
    attrs[0].id = cudaLaunchAttributeProgrammaticStreamSerialization;
    attrs[0].val.programmaticStreamSerializationAllowed = 1;
    cfg.attrs = attrs;
    cfg.numAttrs = 1;
    cudaLaunchKernelEx(&cfg, scale_fused_kernel, inputs, Wlin, out);
}

// round 9
// speedup vs baseline: 1.0566x; 1.0566x over previous
#include <cuda_runtime.h>
#include <cuda_bf16.h>
#include <cstdint>

// Shapes (fixed by the problem)
#define L_DIM 4
#define B_DIM 8
#define C_DIM 256
#define HW    4096           // 64*64
#define LBC   (L_DIM * B_DIM * C_DIM)   // 8192

// Scratch in device globals (no allocations allowed)
__device__ float g_gap[LBC];

// ---------------------------------------------------------------------------
// Kernel 1: GAP over H,W. One block per TWO adjacent planes (8192 contiguous
// f32). 256 threads: warps 0-3 reduce plane A, warps 4-7 plane B, each half
// identical to the proven 128-thread/8-float4 pattern. Halves the grid for
// better scheduling + DRAM page locality.
// ---------------------------------------------------------------------------
__global__ __launch_bounds__(256) void gap_kernel(const float* __restrict__ in) {
    const int pair = blockIdx.x;               // 0..4095
    const int t = threadIdx.x;
    const int half = t >> 7;                   // 0 or 1 -> which plane
    const int tl = t & 127;                    // thread id within half
    const int bc = pair * 2 + half;

    const float4* p = reinterpret_cast<const float4*>(in) + (size_t)bc * (HW / 4);

    float s = 0.0f;
#pragma unroll
    for (int k = 0; k < 8; ++k) {
        float4 v = p[tl + k * 128];
        s += (v.x + v.y) + (v.z + v.w);
    }
#pragma unroll
    for (int o = 16; o > 0; o >>= 1)
        s += __shfl_xor_sync(0xffffffffu, s, o);

    __shared__ float sh[8];                    // one slot per warp
    if ((t & 31) == 0) sh[t >> 5] = s;
    __syncthreads();
    if (tl == 0) {
        const float* base = sh + half * 4;
        g_gap[bc] = (base[0] + base[1] + base[2] + base[3]) * (1.0f / (float)HW);
    }
}

// ---------------------------------------------------------------------------
// Kernel 2 (FUSED attn+scale): each block handles one (l,b,c) plane.
// 8 front-batched plane loads; attn scalar recomputed redundantly under
// their latency; multiply + store. (Identical to the 66.6us R7 version;
// PDL reverted — the overlap contention cost more than the boundary.)
// ---------------------------------------------------------------------------
__global__ __launch_bounds__(128) void scale_fused_kernel(const float* __restrict__ in,
                                                          const float* __restrict__ Wlin,
                                                          float* __restrict__ out) {
    const int bc = blockIdx.x;                 // (l*B + b)*C + c
    const int l = bc >> 11;                    // /2048
    const int b = (bc >> 8) & 7;
    const int c = bc & 255;
    const int t = threadIdx.x;

    const float4* p = reinterpret_cast<const float4*>(in) + (size_t)bc * (HW / 4);
    float4* o = reinterpret_cast<float4*>(out) + (size_t)bc * (HW / 4);

    // ---- Front-batch all 8 plane loads (independent LDG.128 in flight) ----
    float4 v0 = p[t + 0 * 128];
    float4 v1 = p[t + 1 * 128];
    float4 v2 = p[t + 2 * 128];
    float4 v3 = p[t + 3 * 128];
    float4 v4 = p[t + 4 * 128];
    float4 v5 = p[t + 5 * 128];
    float4 v6 = p[t + 6 * 128];
    float4 v7 = p[t + 7 * 128];

    // ---- Compute attn scalar while the plane loads are outstanding ----
    const float* wr = Wlin + (size_t)c * C_DIM;
    float pa0 = 0.f, pa1 = 0.f, pa2 = 0.f, pa3 = 0.f;
#pragma unroll
    for (int j = 0; j < 2; ++j) {
        const int c2 = t + 128 * j;
        const float w = wr[c2];
        pa0 = fmaf(w, g_gap[(0 * B_DIM + b) * C_DIM + c2], pa0);
        pa1 = fmaf(w, g_gap[(1 * B_DIM + b) * C_DIM + c2], pa1);
        pa2 = fmaf(w, g_gap[(2 * B_DIM + b) * C_DIM + c2], pa2);
        pa3 = fmaf(w, g_gap[(3 * B_DIM + b) * C_DIM + c2], pa3);
    }
#pragma unroll
    for (int off = 16; off > 0; off >>= 1) {
        pa0 += __shfl_xor_sync(0xffffffffu, pa0, off);
        pa1 += __shfl_xor_sync(0xffffffffu, pa1, off);
        pa2 += __shfl_xor_sync(0xffffffffu, pa2, off);
        pa3 += __shfl_xor_sync(0xffffffffu, pa3, off);
    }
    __shared__ float sh[4][4];                 // [warp][l']
    const int warp = t >> 5;
    if ((t & 31) == 0) {
        sh[warp][0] = pa0; sh[warp][1] = pa1;
        sh[warp][2] = pa2; sh[warp][3] = pa3;
    }
    __syncthreads();
    const float s0 = sh[0][0] + sh[1][0] + sh[2][0] + sh[3][0];
    const float s1 = sh[0][1] + sh[1][1] + sh[2][1] + sh[3][1];
    const float s2 = sh[0][2] + sh[1][2] + sh[2][2] + sh[3][2];
    const float s3 = sh[0][3] + sh[1][3] + sh[2][3] + sh[3][3];

    const float m  = fmaxf(fmaxf(s0, s1), fmaxf(s2, s3));
    const float e0 = __expf(s0 - m), e1 = __expf(s1 - m);
    const float e2 = __expf(s2 - m), e3 = __expf(s3 - m);
    const float inv = 1.0f / (e0 + e1 + e2 + e3);
    const float el  = (l == 0) ? e0 : (l == 1) ? e1 : (l == 2) ? e2 : e3;
    const float a   = el * inv;

    // ---- Scale and store ----
    v0.x *= a; v0.y *= a; v0.z *= a; v0.w *= a;
    v1.x *= a; v1.y *= a; v1.z *= a; v1.w *= a;
    v2.x *= a; v2.y *= a; v2.z *= a; v2.w *= a;
    v3.x *= a; v3.y *= a; v3.z *= a; v3.w *= a;
    v4.x *= a; v4.y *= a; v4.z *= a; v4.w *= a;
    v5.x *= a; v5.y *= a; v5.z *= a; v5.w *= a;
    v6.x *= a; v6.y *= a; v6.z *= a; v6.w *= a;
    v7.x *= a; v7.y *= a; v7.z *= a; v7.w *= a;

    o[t + 0 * 128] = v0;
    o[t + 1 * 128] = v1;
    o[t + 2 * 128] = v2;
    o[t + 3 * 128] = v3;
    o[t + 4 * 128] = v4;
    o[t + 5 * 128] = v5;
    o[t + 6 * 128] = v6;
    o[t + 7 * 128] = v7;
}

extern "C" void kernel_launch(void* const* d_in, const int* in_sizes, int n_in,
                              void* d_out, int out_size) {
    const float* inputs = (const float*)d_in[0];   // [L,B,C,H,W] f32
    const float* Wlin   = (const float*)d_in[1];   // [C,C] f32
    float* out = (float*)d_out;

    gap_kernel<<<LBC / 2, 256>>>(inputs);
    scale_fused_kernel<<<LBC, 128>>>(inputs, Wlin, out);
}